// round 13
// baseline (speedup 1.0000x reference)
#include <cuda_runtime.h>
#include <cuda_fp16.h>
#include <cstdint>
#include <mma.h>
#include <math.h>

using namespace nvcuda;

#define CCH 512
#define GRP 32
#define AREA 4096
#define BATCH 4
#define EPS 1e-6f

// ---------------- scratch (device globals) ----------------
__device__ __half g_xn  [(size_t)BATCH * CCH * AREA];        // 16 MB  [b][c][pix]
__device__ __half g_qkv [(size_t)BATCH * 3 * CCH * AREA];    // 48 MB  q|k|v per batch
__device__ __half g_h   [(size_t)BATCH * CCH * AREA];        // 16 MB
__device__ float  g_s   [(size_t)BATCH * AREA * AREA];       // 256 MB scores (fp32)
__device__ __half g_p   [(size_t)BATCH * AREA * AREA];       // 128 MB softmax probs (fp16)
__device__ __half g_wqkv[3 * CCH * CCH];
__device__ __half g_wo  [CCH * CCH];
__device__ float  g_bqkv[3 * CCH];

// ---------------- GroupNorm -> half output ----------------
__global__ void groupnorm_kernel(const float* __restrict__ net,
                                 const float* __restrict__ gscale,
                                 const float* __restrict__ gbias,
                                 __half* __restrict__ xn) {
    const int CPG = CCH / GRP;           // 16
    const int NEL = CPG * AREA;          // 65536
    int bg = blockIdx.x;
    int b = bg / GRP, g = bg % GRP;
    const float* x = net + ((size_t)b * CCH + (size_t)g * CPG) * AREA;
    __half* y = xn + ((size_t)b * CCH + (size_t)g * CPG) * AREA;

    int tid = threadIdx.x;
    float s = 0.f, ss = 0.f;
    for (int i = tid; i < NEL; i += blockDim.x) {
        float v = x[i];
        s += v; ss += v * v;
    }
    __shared__ float rs[256], rss[256];
    rs[tid] = s; rss[tid] = ss;
    __syncthreads();
    for (int o = 128; o > 0; o >>= 1) {
        if (tid < o) { rs[tid] += rs[tid + o]; rss[tid] += rss[tid + o]; }
        __syncthreads();
    }
    float mu  = rs[0] / (float)NEL;
    float var = rss[0] / (float)NEL - mu * mu;
    float inv = rsqrtf(var + EPS);

    for (int i = tid; i < NEL; i += blockDim.x) {
        int cl = i / AREA;
        int c  = g * CPG + cl;
        y[i] = __float2half((x[i] - mu) * inv * gscale[c] + gbias[c]);
    }
}

// ---------------- pack weights -> half ----------------
__global__ void pack_kernel(const float* __restrict__ wq, const float* __restrict__ wk,
                            const float* __restrict__ wv, const float* __restrict__ wo,
                            const float* __restrict__ bq, const float* __restrict__ bk,
                            const float* __restrict__ bv,
                            __half* __restrict__ w, __half* __restrict__ woh,
                            float* __restrict__ b) {
    int i = blockIdx.x * blockDim.x + threadIdx.x;
    const int WN = CCH * CCH;
    if (i < WN) {
        w[i]          = __float2half(wq[i]);
        w[i + WN]     = __float2half(wk[i]);
        w[i + 2 * WN] = __float2half(wv[i]);
        woh[i]        = __float2half(wo[i]);
    }
    if (i < CCH) {
        b[i] = bq[i];
        b[i + CCH] = bk[i];
        b[i + 2 * CCH] = bv[i];
    }
}

// ---------------- 3-stage cp.async FP16 WMMA GEMM, 128x128x64 ----------------
// D[m,n] = alpha*sum_k A(m,k)*B(k,n) [+bias[m]] [+res], fp32 accumulate.
// A_COL: A(m,k)=A[k*LDA+m]; B_COL: B(k,n)=B[n*LDB+k].
// OUT_HALF: C is __half*, else float*.
#define BM 128
#define BN 128
#define BK 64
#define NSTAGE 3

template<bool C_> struct CondLay;
template<> struct CondLay<false> { using type = wmma::row_major; };
template<> struct CondLay<true>  { using type = wmma::col_major; };

__device__ __forceinline__ void cp16(void* s, const void* g) {
    unsigned int sa = (unsigned int)__cvta_generic_to_shared(s);
    asm volatile("cp.async.cg.shared.global [%0], [%1], 16;" :: "r"(sa), "l"(g));
}

// smem bytes per instantiation = max(NSTAGE * stage_bytes, 128*132*4 epilogue)
template<bool A_COL, bool B_COL>
struct SmemSize {
    static constexpr int A_ELEMS = A_COL ? BK * 136 : BM * 72;   // halves
    static constexpr int B_ELEMS = B_COL ? BN * 72  : BK * 136;  // halves
    static constexpr int STAGE   = A_ELEMS + B_ELEMS;
    static constexpr int BYTES_PIPE = NSTAGE * STAGE * 2;
    static constexpr int BYTES_EPI  = 128 * 132 * 4;
    static constexpr int BYTES = BYTES_PIPE > BYTES_EPI ? BYTES_PIPE : BYTES_EPI;
};

template<int Kv, int LDA, int LDB, int LDC,
         bool A_COL, bool B_COL, bool HAS_BIAS, bool HAS_RES, bool OUT_HALF>
__global__ void __launch_bounds__(256, 2)
gemm_fp16(const __half* __restrict__ A, const __half* __restrict__ B,
          void* __restrict__ Cv,
          const float* __restrict__ bias, const float* __restrict__ res,
          long strA, long strB, long strC, long strR, float alpha) {
    extern __shared__ __align__(16) char smem_raw[];
    __half* hm = (__half*)smem_raw;
    // half-element tile layouts:
    //  A row-major: [BM][72] ; A col-major: [BK][136]
    //  B row-major: [BK][136]; B col-major: [BN][72]
    constexpr int A_ELEMS = SmemSize<A_COL, B_COL>::A_ELEMS;
    constexpr int STAGE   = SmemSize<A_COL, B_COL>::STAGE;
    constexpr int KT      = Kv / BK;

    const int bz = blockIdx.z;
    A += (size_t)bz * strA;
    B += (size_t)bz * strB;
    if (HAS_RES) res += (size_t)bz * strR;

    const int bm = blockIdx.y * BM;
    const int bn = blockIdx.x * BN;
    const int tid = threadIdx.x;
    const int warp = tid >> 5;
    const int wm = warp >> 1;    // 0..3
    const int wn = warp & 1;     // 0..1

    wmma::fragment<wmma::accumulator, 16, 16, 16, float> acc[2][4];
    #pragma unroll
    for (int i = 0; i < 2; i++)
        #pragma unroll
        for (int j = 0; j < 4; j++)
            wmma::fill_fragment(acc[i][j], 0.0f);

    auto load_tiles = [&](int slot, int k0) {
        __half* sA = hm + slot * STAGE;
        __half* sB = sA + A_ELEMS;
        if (A_COL) {
            // [BK rows][BM halves] -> sA[k*136 + m]   (1024 chunks of 8 halves)
            #pragma unroll
            for (int c = tid; c < 1024; c += 256) {
                int k = c >> 4, m8 = (c & 15) << 3;
                cp16(&sA[k * 136 + m8], &A[(size_t)(k0 + k) * LDA + bm + m8]);
            }
        } else {
            // [BM rows][BK halves] -> sA[m*72 + k]
            #pragma unroll
            for (int c = tid; c < 1024; c += 256) {
                int m = c >> 3, k8 = (c & 7) << 3;
                cp16(&sA[m * 72 + k8], &A[(size_t)(bm + m) * LDA + k0 + k8]);
            }
        }
        if (B_COL) {
            // [BN rows][BK halves] -> sB[n*72 + k]
            #pragma unroll
            for (int c = tid; c < 1024; c += 256) {
                int n = c >> 3, k8 = (c & 7) << 3;
                cp16(&sB[n * 72 + k8], &B[(size_t)(bn + n) * LDB + k0 + k8]);
            }
        } else {
            // [BK rows][BN halves] -> sB[k*136 + n]
            #pragma unroll
            for (int c = tid; c < 1024; c += 256) {
                int k = c >> 4, n8 = (c & 15) << 3;
                cp16(&sB[k * 136 + n8], &B[(size_t)(k0 + k) * LDB + bn + n8]);
            }
        }
    };

    // prologue
    #pragma unroll
    for (int s = 0; s < NSTAGE - 1; s++) {
        if (s < KT) load_tiles(s, s * BK);
        asm volatile("cp.async.commit_group;");
    }

    using ALay = typename CondLay<A_COL>::type;
    using BLay = typename CondLay<B_COL>::type;

    for (int kt = 0; kt < KT; kt++) {
        if (kt < KT - 1) asm volatile("cp.async.wait_group %0;" :: "n"(NSTAGE - 2));
        else             asm volatile("cp.async.wait_group 0;");
        __syncthreads();

        if (kt + NSTAGE - 1 < KT)
            load_tiles((kt + NSTAGE - 1) % NSTAGE, (kt + NSTAGE - 1) * BK);
        asm volatile("cp.async.commit_group;");

        __half* sA = hm + (kt % NSTAGE) * STAGE;
        __half* sB = sA + A_ELEMS;

        #pragma unroll
        for (int kk = 0; kk < BK; kk += 16) {
            wmma::fragment<wmma::matrix_a, 16, 16, 16, __half, ALay> fa[2];
            wmma::fragment<wmma::matrix_b, 16, 16, 16, __half, BLay> fb[4];
            #pragma unroll
            for (int im = 0; im < 2; im++) {
                int m0 = wm * 32 + im * 16;
                const __half* p = A_COL ? (sA + kk * 136 + m0) : (sA + m0 * 72 + kk);
                wmma::load_matrix_sync(fa[im], p, A_COL ? 136 : 72);
            }
            #pragma unroll
            for (int in_ = 0; in_ < 4; in_++) {
                int n0 = wn * 64 + in_ * 16;
                const __half* p = B_COL ? (sB + n0 * 72 + kk) : (sB + kk * 136 + n0);
                wmma::load_matrix_sync(fb[in_], p, B_COL ? 72 : 136);
            }
            #pragma unroll
            for (int im = 0; im < 2; im++)
                #pragma unroll
                for (int in_ = 0; in_ < 4; in_++)
                    wmma::mma_sync(acc[im][in_], fa[im], fb[in_], acc[im][in_]);
        }
    }
    __syncthreads();   // done with stage buffers before reuse as sC

    // ---- epilogue: stage accums in smem (fp32), then write ----
    float* sC = (float*)smem_raw;   // [128][132]
    #pragma unroll
    for (int im = 0; im < 2; im++)
        #pragma unroll
        for (int in_ = 0; in_ < 4; in_++)
            wmma::store_matrix_sync(sC + (wm * 32 + im * 16) * 132 + wn * 64 + in_ * 16,
                                    acc[im][in_], 132, wmma::mem_row_major);
    __syncthreads();

    #pragma unroll
    for (int i = tid; i < BM * BN / 4; i += 256) {
        int m = i >> 5, n4 = (i & 31) << 2;
        float4 v;
        v.x = alpha * sC[m * 132 + n4 + 0];
        v.y = alpha * sC[m * 132 + n4 + 1];
        v.z = alpha * sC[m * 132 + n4 + 2];
        v.w = alpha * sC[m * 132 + n4 + 3];
        if (HAS_BIAS) {
            float bb = bias[bm + m];
            v.x += bb; v.y += bb; v.z += bb; v.w += bb;
        }
        if (HAS_RES) {
            const float4 r = *(const float4*)&res[(size_t)(bm + m) * LDC + bn + n4];
            v.x += r.x; v.y += r.y; v.z += r.z; v.w += r.w;
        }
        if (OUT_HALF) {
            __half* Ch = (__half*)Cv + (size_t)bz * strC;
            __half2 h0 = __floats2half2_rn(v.x, v.y);
            __half2 h1 = __floats2half2_rn(v.z, v.w);
            uint2 pk = { *(uint32_t*)&h0, *(uint32_t*)&h1 };
            *(uint2*)&Ch[(size_t)(bm + m) * LDC + bn + n4] = pk;
        } else {
            float* Cf = (float*)Cv + (size_t)bz * strC;
            *(float4*)&Cf[(size_t)(bm + m) * LDC + bn + n4] = v;
        }
    }
}

// ---------------- row softmax: fp32 in, fp16 out ----------------
__global__ void softmax_kernel(const float* __restrict__ S, __half* __restrict__ P) {
    const float* row = S + (size_t)blockIdx.x * AREA;
    __half* prow = P + (size_t)blockIdx.x * AREA;
    __shared__ float buf[AREA];
    __shared__ float red[256];
    int tid = threadIdx.x;

    float m = -INFINITY;
    for (int i = tid; i < AREA; i += 256) {
        float v = row[i];
        buf[i] = v;
        m = fmaxf(m, v);
    }
    red[tid] = m;
    __syncthreads();
    for (int o = 128; o > 0; o >>= 1) {
        if (tid < o) red[tid] = fmaxf(red[tid], red[tid + o]);
        __syncthreads();
    }
    m = red[0];
    __syncthreads();

    float s = 0.f;
    for (int i = tid; i < AREA; i += 256) {
        float e = __expf(buf[i] - m);
        buf[i] = e;
        s += e;
    }
    red[tid] = s;
    __syncthreads();
    for (int o = 128; o > 0; o >>= 1) {
        if (tid < o) red[tid] += red[tid + o];
        __syncthreads();
    }
    float inv = 1.0f / red[0];
    __syncthreads();

    for (int i = tid; i < AREA; i += 256)
        prow[i] = __float2half(buf[i] * inv);
}

// ---------------- launch ----------------
extern "C" void kernel_launch(void* const* d_in, const int* in_sizes, int n_in,
                              void* d_out, int out_size) {
    const float* net      = (const float*)d_in[0];
    const float* gn_scale = (const float*)d_in[1];
    const float* gn_bias  = (const float*)d_in[2];
    const float* wq = (const float*)d_in[3];
    const float* bq = (const float*)d_in[4];
    const float* wk = (const float*)d_in[5];
    const float* bk = (const float*)d_in[6];
    const float* wv = (const float*)d_in[7];
    const float* bv = (const float*)d_in[8];
    const float* wo = (const float*)d_in[9];
    const float* bo = (const float*)d_in[10];
    float* out = (float*)d_out;

    __half *xn, *qkv, *h, *p, *wqkv, *woh;
    float *s, *bqkv;
    cudaGetSymbolAddress((void**)&xn,   g_xn);
    cudaGetSymbolAddress((void**)&qkv,  g_qkv);
    cudaGetSymbolAddress((void**)&h,    g_h);
    cudaGetSymbolAddress((void**)&s,    g_s);
    cudaGetSymbolAddress((void**)&p,    g_p);
    cudaGetSymbolAddress((void**)&wqkv, g_wqkv);
    cudaGetSymbolAddress((void**)&woh,  g_wo);
    cudaGetSymbolAddress((void**)&bqkv, g_bqkv);

    // instantiations
    auto kQKV = gemm_fp16<CCH,  CCH,  AREA, AREA, false, false, true,  false, true >;
    auto kSC  = gemm_fp16<CCH,  AREA, AREA, AREA, true,  false, false, false, false>;
    auto kPV  = gemm_fp16<AREA, AREA, AREA, AREA, false, true,  false, false, true >;
    auto kOUT = gemm_fp16<CCH,  CCH,  AREA, AREA, false, false, true,  true,  false>;

    const int SM_FF = SmemSize<false, false>::BYTES;  // QKV / OUT
    const int SM_TF = SmemSize<true,  false>::BYTES;  // score
    const int SM_FT = SmemSize<false, true >::BYTES;  // PV

    cudaFuncSetAttribute(kQKV, cudaFuncAttributeMaxDynamicSharedMemorySize, SM_FF);
    cudaFuncSetAttribute(kSC,  cudaFuncAttributeMaxDynamicSharedMemorySize, SM_TF);
    cudaFuncSetAttribute(kPV,  cudaFuncAttributeMaxDynamicSharedMemorySize, SM_FT);
    cudaFuncSetAttribute(kOUT, cudaFuncAttributeMaxDynamicSharedMemorySize, SM_FF);

    const long sBC  = (long)CCH * AREA;
    const long s3BC = (long)3 * CCH * AREA;
    const long sSS  = (long)AREA * AREA;
    const float inv_sqrt_c = 1.0f / sqrtf((float)CCH);

    pack_kernel<<<(CCH * CCH + 255) / 256, 256>>>(wq, wk, wv, wo, bq, bk, bv,
                                                  wqkv, woh, bqkv);
    groupnorm_kernel<<<BATCH * GRP, 256>>>(net, gn_scale, gn_bias, xn);

    // QKV = Wqkv @ xn + b  (M=1536, N=4096, K=512), half out
    {
        dim3 g(AREA / BN, (3 * CCH) / BM, BATCH);
        kQKV<<<g, 256, SM_FF>>>(wqkv, xn, qkv, bqkv, nullptr, 0, sBC, s3BC, 0, 1.0f);
    }

    const __half* q = qkv;
    const __half* k = qkv + (size_t)CCH * AREA;
    const __half* v = qkv + (size_t)2 * CCH * AREA;

    // S = (Q^T K) / sqrt(C), fp32 out
    {
        dim3 g(AREA / BN, AREA / BM, BATCH);
        kSC<<<g, 256, SM_TF>>>(q, k, s, nullptr, nullptr, s3BC, s3BC, sSS, 0, inv_sqrt_c);
    }

    softmax_kernel<<<BATCH * AREA, 256>>>(s, p);

    // H = V @ P^T, half out
    {
        dim3 g(AREA / BN, CCH / BM, BATCH);
        kPV<<<g, 256, SM_FT>>>(v, p, h, nullptr, nullptr, s3BC, sSS, sBC, 0, 1.0f);
    }

    // out = net + Wo @ H + bo, fp32 out
    {
        dim3 g(AREA / BN, CCH / BM, BATCH);
        kOUT<<<g, 256, SM_FF>>>(woh, h, out, bo, net, 0, sBC, sBC, sBC, 1.0f);
    }
}